// round 1
// baseline (speedup 1.0000x reference)
#include <cuda_runtime.h>
#include <cstdint>

typedef unsigned long long u64;

#define NQ 16384
#define NB 128
#define NF 64
#define HD 128
#define EPSF 1e-8f

#define THREADS 512
#define WARPS_PER_CTA 16

// Packed probe tables, written by prep kernel.
// Pair p couples b=p and b=p+64.
// g_probeA[f][p] = {P_real[p], P_real[p+64], P_imag[p], P_imag[p+64]}
// g_probeB[f][p] = {w[p],      w[p+64],      mw[p],     mw[p+64]}
__device__ float g_probeA[NF * 64 * 4];
__device__ float g_probeB[NF * 64 * 4];

// ---------- f32x2 helpers (packed fp32 pair ops, Blackwell) ----------
__device__ __forceinline__ u64 f2pk(float lo, float hi) {
    u64 r; asm("mov.b64 %0, {%1,%2};" : "=l"(r) : "f"(lo), "f"(hi)); return r;
}
__device__ __forceinline__ void f2upk(float& lo, float& hi, u64 v) {
    asm("mov.b64 {%0,%1}, %2;" : "=f"(lo), "=f"(hi) : "l"(v));
}
__device__ __forceinline__ u64 f2add(u64 a, u64 b) {
    u64 d; asm("add.rn.f32x2 %0, %1, %2;" : "=l"(d) : "l"(a), "l"(b)); return d;
}
__device__ __forceinline__ u64 f2fma(u64 a, u64 b, u64 c) {
    u64 d; asm("fma.rn.f32x2 %0, %1, %2, %3;" : "=l"(d) : "l"(a), "l"(b), "l"(c)); return d;
}
__device__ __forceinline__ float sqrt_apx(float x) {
    float r; asm("sqrt.approx.f32 %0, %1;" : "=f"(r) : "f"(x)); return r;
}
__device__ __forceinline__ float rcp_apx(float x) {
    float r; asm("rcp.approx.f32 %0, %1;" : "=f"(r) : "f"(x)); return r;
}
__device__ __forceinline__ uint32_t su32(const void* p) {
    uint32_t a;
    asm("{ .reg .u64 t; cvta.to.shared.u64 t, %1; cvt.u32.u64 %0, t; }"
        : "=r"(a) : "l"(p));
    return a;
}

// ---------- prep kernel: probe normalize + rotate + softplus, pack ----------
__global__ void prep_kernel(const float* __restrict__ probes,
                            const float* __restrict__ angles,
                            const float* __restrict__ qw,
                            const float* __restrict__ qmw) {
    int b = threadIdx.x;  // 0..127
    if (b >= NB) return;
    float ss = 0.0f;
#pragma unroll 8
    for (int i = 0; i < HD; i++) {
        float x = probes[b * HD + i];
        ss = fmaf(x, x, ss);
    }
    float inv = 1.0f / (sqrtf(ss) + EPSF);
    int p = b & 63;
    int hi = b >> 6;
    for (int f = 0; f < NF; f++) {
        float pr = probes[b * HD + f] * inv;
        float pi = probes[b * HD + NF + f] * inv;
        float ang = angles[f];
        float c = cosf(ang), s = sinf(ang);
        float Pr = pr * c - pi * s;
        float Pi = pr * s + pi * c;
        float x = qw[b * NF + f];
        float sp = (x > 20.0f) ? x : log1pf(expf(x));
        float w = -sp;
        float mw = qmw[b * NF + f];
        int base = (f * 64 + p) * 4;
        g_probeA[base + 0 + hi] = Pr;
        g_probeA[base + 2 + hi] = Pi;
        g_probeB[base + 0 + hi] = w;
        g_probeB[base + 2 + hi] = mw;
    }
}

// ---------- SMEM layout (float offsets) ----------
#define OFF_SA  0                  // probeA: 64*64 float4 = 16384 floats (64KB)
#define OFF_SB  16384              // probeB: 16384 floats (64KB)
#define OFF_QTA 32768              // per-warp {-qr,-qr,-qi,-qi}: 16*64*4 = 4096 floats
#define OFF_QTM 36864              // per-warp {qm,qm}: 16*64*2 = 2048 floats
#define OFF_QN  38912              // per-warp qn scratch: 16*128 = 2048 floats
#define SMEM_FLOATS 40960          // 160 KB

__global__ __launch_bounds__(THREADS, 1)
void main_kernel(const float* __restrict__ Q,
                 const float* __restrict__ bias,
                 float* __restrict__ out) {
    extern __shared__ float sm[];
    const int tid  = threadIdx.x;
    const int warp = tid >> 5;
    const int lane = tid & 31;

    // Stage probe tables into SMEM
    {
        const float4* gA = (const float4*)g_probeA;
        const float4* gB = (const float4*)g_probeB;
        float4* sA4 = (float4*)(sm + OFF_SA);
        float4* sB4 = (float4*)(sm + OFF_SB);
#pragma unroll
        for (int i = tid; i < NF * 64; i += THREADS) {
            sA4[i] = gA[i];
            sB4[i] = gB[i];
        }
    }

    // Bias packs (pair0 = {b=lane, b=lane+64}, pair1 = {b=lane+32, b=lane+96})
    const u64 bias0 = f2pk(bias[lane],      bias[lane + 64]);
    const u64 bias1 = f2pk(bias[lane + 32], bias[lane + 96]);
    const u64 EPS2  = f2pk(EPSF, EPSF);

    __syncthreads();

    const uint32_t sbase = su32(sm);
    const uint32_t aA0 = sbase + (uint32_t)lane * 16u;                     // probeA, pair=lane
    const uint32_t aB0 = sbase + (uint32_t)OFF_SB * 4u + (uint32_t)lane * 16u;
    const uint32_t aQA = sbase + ((uint32_t)OFF_QTA + (uint32_t)warp * 256u) * 4u;
    const uint32_t aQM = sbase + ((uint32_t)OFF_QTM + (uint32_t)warp * 128u) * 4u;
    float* qn  = sm + OFF_QN + warp * 128;
    float4* qtA = (float4*)(sm + OFF_QTA + warp * 256);
    float2* qtM = (float2*)(sm + OFF_QTM + warp * 128);

    const int nwarps = (gridDim.x * blockDim.x) >> 5;
    const int gw = blockIdx.x * WARPS_PER_CTA + warp;

    for (int q = gw; q < NQ; q += nwarps) {
        // ---- per-q prep: normalize Q row, build per-f packed tables ----
        const float4* Qv = (const float4*)(Q + (size_t)q * HD);
        float4 v = Qv[lane];
        float ss = fmaf(v.x, v.x, fmaf(v.y, v.y, fmaf(v.z, v.z, v.w * v.w)));
#pragma unroll
        for (int o = 16; o; o >>= 1) ss += __shfl_xor_sync(0xffffffffu, ss, o);
        float inv = rcp_apx(sqrt_apx(ss) + EPSF);
        ((float4*)qn)[lane] = make_float4(v.x * inv, v.y * inv, v.z * inv, v.w * inv);
        __syncwarp();
#pragma unroll
        for (int k = 0; k < 2; k++) {
            int f = lane + k * 32;
            float qr = qn[f];
            float qi = qn[f + 64];
            float qm = sqrt_apx(fmaf(qr, qr, fmaf(qi, qi, EPSF)));
            qtA[f] = make_float4(-qr, -qr, -qi, -qi);  // negated: sub via add.f32x2
            qtM[f] = make_float2(qm, qm);
        }
        __syncwarp();

        // ---- main loop over f: 4 b's per lane as 2 packed pairs ----
        u64 acc0 = bias0, acc1 = bias1;
#pragma unroll 4
        for (int f = 0; f < NF; f++) {
            u64 nqr, nqi, qm2;
            asm("ld.shared.v2.b64 {%0,%1}, [%2];"
                : "=l"(nqr), "=l"(nqi) : "r"(aQA + (uint32_t)f * 16u));
            asm("ld.shared.b64 %0, [%1];"
                : "=l"(qm2) : "r"(aQM + (uint32_t)f * 8u));

            const uint32_t fo = (uint32_t)f * 1024u;
            u64 Pr0, Pi0, w0, mw0, Pr1, Pi1, w1, mw1;
            asm("ld.shared.v2.b64 {%0,%1}, [%2];" : "=l"(Pr0), "=l"(Pi0) : "r"(aA0 + fo));
            asm("ld.shared.v2.b64 {%0,%1}, [%2];" : "=l"(w0),  "=l"(mw0) : "r"(aB0 + fo));
            asm("ld.shared.v2.b64 {%0,%1}, [%2];" : "=l"(Pr1), "=l"(Pi1) : "r"(aA0 + fo + 512u));
            asm("ld.shared.v2.b64 {%0,%1}, [%2];" : "=l"(w1),  "=l"(mw1) : "r"(aB0 + fo + 512u));

            // pair 0
            {
                u64 er = f2add(Pr0, nqr);
                u64 ei = f2add(Pi0, nqi);
                u64 d2 = f2fma(er, er, f2fma(ei, ei, EPS2));
                float lo, hi;
                f2upk(lo, hi, d2);
                u64 dist = f2pk(sqrt_apx(lo), sqrt_apx(hi));
                acc0 = f2fma(dist, w0, acc0);
                acc0 = f2fma(qm2, mw0, acc0);
            }
            // pair 1
            {
                u64 er = f2add(Pr1, nqr);
                u64 ei = f2add(Pi1, nqi);
                u64 d2 = f2fma(er, er, f2fma(ei, ei, EPS2));
                float lo, hi;
                f2upk(lo, hi, d2);
                u64 dist = f2pk(sqrt_apx(lo), sqrt_apx(hi));
                acc1 = f2fma(dist, w1, acc1);
                acc1 = f2fma(qm2, mw1, acc1);
            }
        }

        float o0, o1, o2, o3;
        f2upk(o0, o1, acc0);
        f2upk(o2, o3, acc1);
        float* orow = out + (size_t)q * NB;
        orow[lane]      = o0;
        orow[lane + 64] = o1;
        orow[lane + 32] = o2;
        orow[lane + 96] = o3;
    }
}

extern "C" void kernel_launch(void* const* d_in, const int* in_sizes, int n_in,
                              void* d_out, int out_size) {
    const float* Q      = (const float*)d_in[0];
    const float* angles = (const float*)d_in[1];
    const float* probes = (const float*)d_in[2];
    const float* qw     = (const float*)d_in[3];
    const float* qmw    = (const float*)d_in[4];
    const float* qbias  = (const float*)d_in[5];
    float* out = (float*)d_out;

    static_assert(SMEM_FLOATS * sizeof(float) == 163840, "smem layout");
    cudaFuncSetAttribute(main_kernel,
                         cudaFuncAttributeMaxDynamicSharedMemorySize,
                         SMEM_FLOATS * (int)sizeof(float));

    int sms = 148;
    cudaDeviceGetAttribute(&sms, cudaDevAttrMultiProcessorCount, 0);

    prep_kernel<<<1, NB>>>(probes, angles, qw, qmw);
    main_kernel<<<sms, THREADS, SMEM_FLOATS * sizeof(float)>>>(Q, qbias, out);
}

// round 3
// speedup vs baseline: 1.9845x; 1.9845x over previous
#include <cuda_runtime.h>
#include <cstdint>

typedef unsigned long long u64;

#define NQ 16384
#define NB 128
#define NF 64
#define HD 128
#define EPSF 1e-8f

#define THREADS 512
#define WARPS_PER_CTA 16
#define QB 4

// Packed probe tables, written by prep kernel.
// Pair p couples b=p and b=p+64.
// g_probeA[f][p] = {P_real[p], P_real[p+64], P_imag[p], P_imag[p+64]}
// g_probeB[f][p] = {w[p],      w[p+64],      mw[p],     mw[p+64]}
__device__ float g_probeA[NF * 64 * 4];
__device__ float g_probeB[NF * 64 * 4];

// ---------- f32x2 helpers ----------
__device__ __forceinline__ u64 f2pk(float lo, float hi) {
    u64 r; asm("mov.b64 %0, {%1,%2};" : "=l"(r) : "f"(lo), "f"(hi)); return r;
}
__device__ __forceinline__ void f2upk(float& lo, float& hi, u64 v) {
    asm("mov.b64 {%0,%1}, %2;" : "=f"(lo), "=f"(hi) : "l"(v));
}
__device__ __forceinline__ u64 f2add(u64 a, u64 b) {
    u64 d; asm("add.rn.f32x2 %0, %1, %2;" : "=l"(d) : "l"(a), "l"(b)); return d;
}
__device__ __forceinline__ u64 f2fma(u64 a, u64 b, u64 c) {
    u64 d; asm("fma.rn.f32x2 %0, %1, %2, %3;" : "=l"(d) : "l"(a), "l"(b), "l"(c)); return d;
}
__device__ __forceinline__ float sqrt_apx(float x) {
    float r; asm("sqrt.approx.f32 %0, %1;" : "=f"(r) : "f"(x)); return r;
}
__device__ __forceinline__ float rcp_apx(float x) {
    float r; asm("rcp.approx.f32 %0, %1;" : "=f"(r) : "f"(x)); return r;
}
__device__ __forceinline__ uint32_t su32(const void* p) {
    uint32_t a;
    asm("{ .reg .u64 t; cvta.to.shared.u64 t, %1; cvt.u32.u64 %0, t; }"
        : "=r"(a) : "l"(p));
    return a;
}

// ---------- prep: one block per probe b, one thread per f ----------
__global__ __launch_bounds__(64)
void prep_kernel(const float* __restrict__ probes,
                 const float* __restrict__ angles,
                 const float* __restrict__ qw,
                 const float* __restrict__ qmw) {
    __shared__ float red[2];
    const int b = blockIdx.x;   // 0..127
    const int f = threadIdx.x;  // 0..63
    const int warp = f >> 5;
    const int lane = f & 31;

    float x0 = probes[b * HD + f];
    float x1 = probes[b * HD + NF + f];
    float ss = fmaf(x0, x0, x1 * x1);
#pragma unroll
    for (int o = 16; o; o >>= 1) ss += __shfl_xor_sync(0xffffffffu, ss, o);
    if (lane == 0) red[warp] = ss;
    __syncthreads();
    float inv = 1.0f / (sqrtf(red[0] + red[1]) + EPSF);

    float pr = x0 * inv;
    float pi = x1 * inv;
    float c, s;
    sincosf(angles[f], &s, &c);
    float Pr = pr * c - pi * s;
    float Pi = pr * s + pi * c;
    float xw = qw[b * NF + f];
    float sp = (xw > 20.0f) ? xw : log1pf(expf(xw));
    float w = -sp;
    float mw = qmw[b * NF + f];

    int p = b & 63;
    int hi = b >> 6;
    int base = (f * 64 + p) * 4;
    g_probeA[base + 0 + hi] = Pr;
    g_probeA[base + 2 + hi] = Pi;
    g_probeB[base + 0 + hi] = w;
    g_probeB[base + 2 + hi] = mw;
}

// ---------- SMEM layout (float offsets) ----------
#define OFF_SA  0                  // probeA: 16384 floats (64KB)
#define OFF_SB  16384              // probeB: 16384 floats (64KB)
#define OFF_QT  32768              // q-tables: 16 warps * QB * 64 * float4 = 16384 floats (64KB)
#define OFF_QN  49152              // per-warp qn scratch: 16*128 = 2048 floats
#define SMEM_FLOATS 51200          // 200 KB

__global__ __launch_bounds__(THREADS, 1)
void main_kernel(const float* __restrict__ Q,
                 const float* __restrict__ bias,
                 float* __restrict__ out) {
    extern __shared__ float sm[];
    const int tid  = threadIdx.x;
    const int warp = tid >> 5;
    const int lane = tid & 31;

    // Stage probe tables into SMEM
    {
        const float4* gA = (const float4*)g_probeA;
        const float4* gB = (const float4*)g_probeB;
        float4* sA4 = (float4*)(sm + OFF_SA);
        float4* sB4 = (float4*)(sm + OFF_SB);
#pragma unroll
        for (int i = tid; i < NF * 64; i += THREADS) {
            sA4[i] = gA[i];
            sB4[i] = gB[i];
        }
    }

    const u64 bias0 = f2pk(bias[lane],      bias[lane + 64]);
    const u64 bias1 = f2pk(bias[lane + 32], bias[lane + 96]);
    const u64 EPS2  = f2pk(EPSF, EPSF);

    __syncthreads();

    const uint32_t sbase = su32(sm);
    const uint32_t aA0 = sbase + (uint32_t)lane * 16u;
    const uint32_t aB0 = sbase + (uint32_t)OFF_SB * 4u + (uint32_t)lane * 16u;
    // per-warp q-table region: QB*64 float4 = 4096 bytes per warp
    const uint32_t aQT = sbase + (uint32_t)OFF_QT * 4u + (uint32_t)warp * 4096u;
    float*  qn = sm + OFF_QN + warp * 128;
    float4* qt = (float4*)(sm + OFF_QT + warp * QB * 64 * 4);

    const int ngroups = NQ / QB;                       // 4096
    const int gstride = gridDim.x * WARPS_PER_CTA;
    int group = blockIdx.x * WARPS_PER_CTA + warp;

    for (; group < ngroups; group += gstride) {
        const int q0 = group * QB;

        // ---- per-group prep: normalize QB rows, build q-tables ----
#pragma unroll
        for (int j = 0; j < QB; j++) {
            const float4* Qv = (const float4*)(Q + (size_t)(q0 + j) * HD);
            float4 v = Qv[lane];
            float ss = fmaf(v.x, v.x, fmaf(v.y, v.y, fmaf(v.z, v.z, v.w * v.w)));
#pragma unroll
            for (int o = 16; o; o >>= 1) ss += __shfl_xor_sync(0xffffffffu, ss, o);
            float inv = rcp_apx(sqrt_apx(ss) + EPSF);
            ((float4*)qn)[lane] = make_float4(v.x * inv, v.y * inv, v.z * inv, v.w * inv);
            __syncwarp();
#pragma unroll
            for (int k = 0; k < 2; k++) {
                int f = lane + k * 32;
                float qr = qn[f];
                float qi = qn[f + 64];
                float qm = sqrt_apx(fmaf(qr, qr, fmaf(qi, qi, EPSF)));
                qt[j * 64 + f] = make_float4(-qr, -qi, qm, 0.0f);
            }
            __syncwarp();
        }

        // ---- inner loop over f: QB q's, 4 b's per lane (2 packed pairs) ----
        u64 acc0[QB], acc1[QB];
#pragma unroll
        for (int j = 0; j < QB; j++) { acc0[j] = bias0; acc1[j] = bias1; }

#pragma unroll 2
        for (int f = 0; f < NF; f++) {
            const uint32_t fo = (uint32_t)f * 1024u;
            u64 Pr0, Pi0, w0, mw0, Pr1, Pi1, w1, mw1;
            asm("ld.shared.v2.b64 {%0,%1}, [%2];" : "=l"(Pr0), "=l"(Pi0) : "r"(aA0 + fo));
            asm("ld.shared.v2.b64 {%0,%1}, [%2];" : "=l"(w0),  "=l"(mw0) : "r"(aB0 + fo));
            asm("ld.shared.v2.b64 {%0,%1}, [%2];" : "=l"(Pr1), "=l"(Pi1) : "r"(aA0 + fo + 512u));
            asm("ld.shared.v2.b64 {%0,%1}, [%2];" : "=l"(w1),  "=l"(mw1) : "r"(aB0 + fo + 512u));

            float tx[QB], ty[QB], tz[QB], tw_[QB];
#pragma unroll
            for (int j = 0; j < QB; j++) {
                // j stride: 64 entries * 16B = 1024 bytes (matches qt[j*64+f] writes)
                asm("ld.shared.v4.f32 {%0,%1,%2,%3}, [%4];"
                    : "=f"(tx[j]), "=f"(ty[j]), "=f"(tz[j]), "=f"(tw_[j])
                    : "r"(aQT + (uint32_t)j * 1024u + (uint32_t)f * 16u));
            }

#pragma unroll
            for (int j = 0; j < QB; j++) {
                u64 nqr = f2pk(tx[j], tx[j]);
                u64 nqi = f2pk(ty[j], ty[j]);
                u64 qm2 = f2pk(tz[j], tz[j]);
                // pair 0
                {
                    u64 er = f2add(Pr0, nqr);
                    u64 ei = f2add(Pi0, nqi);
                    u64 d2 = f2fma(er, er, f2fma(ei, ei, EPS2));
                    float lo, hi; f2upk(lo, hi, d2);
                    u64 dist = f2pk(sqrt_apx(lo), sqrt_apx(hi));
                    acc0[j] = f2fma(dist, w0, acc0[j]);
                    acc0[j] = f2fma(qm2, mw0, acc0[j]);
                }
                // pair 1
                {
                    u64 er = f2add(Pr1, nqr);
                    u64 ei = f2add(Pi1, nqi);
                    u64 d2 = f2fma(er, er, f2fma(ei, ei, EPS2));
                    float lo, hi; f2upk(lo, hi, d2);
                    u64 dist = f2pk(sqrt_apx(lo), sqrt_apx(hi));
                    acc1[j] = f2fma(dist, w1, acc1[j]);
                    acc1[j] = f2fma(qm2, mw1, acc1[j]);
                }
            }
        }

#pragma unroll
        for (int j = 0; j < QB; j++) {
            float o0, o1, o2, o3;
            f2upk(o0, o1, acc0[j]);
            f2upk(o2, o3, acc1[j]);
            float* orow = out + (size_t)(q0 + j) * NB;
            orow[lane]      = o0;
            orow[lane + 64] = o1;
            orow[lane + 32] = o2;
            orow[lane + 96] = o3;
        }
    }
}

extern "C" void kernel_launch(void* const* d_in, const int* in_sizes, int n_in,
                              void* d_out, int out_size) {
    const float* Q      = (const float*)d_in[0];
    const float* angles = (const float*)d_in[1];
    const float* probes = (const float*)d_in[2];
    const float* qw     = (const float*)d_in[3];
    const float* qmw    = (const float*)d_in[4];
    const float* qbias  = (const float*)d_in[5];
    float* out = (float*)d_out;

    static_assert(SMEM_FLOATS * sizeof(float) == 204800, "smem layout");
    cudaFuncSetAttribute(main_kernel,
                         cudaFuncAttributeMaxDynamicSharedMemorySize,
                         SMEM_FLOATS * (int)sizeof(float));

    int sms = 148;
    cudaDeviceGetAttribute(&sms, cudaDevAttrMultiProcessorCount, 0);

    prep_kernel<<<NB, 64>>>(probes, angles, qw, qmw);
    main_kernel<<<sms, THREADS, SMEM_FLOATS * sizeof(float)>>>(Q, qbias, out);
}

// round 4
// speedup vs baseline: 2.1768x; 1.0969x over previous
#include <cuda_runtime.h>
#include <cstdint>

typedef unsigned long long u64;

#define NQ 16384
#define NB 128
#define NF 64
#define HD 128
#define EPSF 1e-8f

#define THREADS 768
#define WARPS_PER_CTA 24
#define PAIRS_PER_CTA 12
#define MAXQ 5   // max q's per batch (template JN <= 5)

// Packed probe tables (prep kernel output).
// Pair p couples b=p and b=p+64.
// g_probeA[f][p] = {P_real[p], P_real[p+64], P_imag[p], P_imag[p+64]}
// g_probeB[f][p] = {w[p],      w[p+64],      mw[p],     mw[p+64]}
__device__ float g_probeA[NF * 64 * 4];
__device__ float g_probeB[NF * 64 * 4];

// ---------- f32x2 helpers ----------
__device__ __forceinline__ u64 f2pk(float lo, float hi) {
    u64 r; asm("mov.b64 %0, {%1,%2};" : "=l"(r) : "f"(lo), "f"(hi)); return r;
}
__device__ __forceinline__ void f2upk(float& lo, float& hi, u64 v) {
    asm("mov.b64 {%0,%1}, %2;" : "=f"(lo), "=f"(hi) : "l"(v));
}
__device__ __forceinline__ u64 f2add(u64 a, u64 b) {
    u64 d; asm("add.rn.f32x2 %0, %1, %2;" : "=l"(d) : "l"(a), "l"(b)); return d;
}
__device__ __forceinline__ u64 f2fma(u64 a, u64 b, u64 c) {
    u64 d; asm("fma.rn.f32x2 %0, %1, %2, %3;" : "=l"(d) : "l"(a), "l"(b), "l"(c)); return d;
}
__device__ __forceinline__ float sqrt_apx(float x) {
    float r; asm("sqrt.approx.f32 %0, %1;" : "=f"(r) : "f"(x)); return r;
}
__device__ __forceinline__ float rcp_apx(float x) {
    float r; asm("rcp.approx.f32 %0, %1;" : "=f"(r) : "f"(x)); return r;
}
__device__ __forceinline__ uint32_t su32(const void* p) {
    uint32_t a;
    asm("{ .reg .u64 t; cvta.to.shared.u64 t, %1; cvt.u32.u64 %0, t; }"
        : "=r"(a) : "l"(p));
    return a;
}

// ---------- prep: one block per probe b, one thread per f ----------
__global__ __launch_bounds__(64)
void prep_kernel(const float* __restrict__ probes,
                 const float* __restrict__ angles,
                 const float* __restrict__ qw,
                 const float* __restrict__ qmw) {
    __shared__ float red[2];
    const int b = blockIdx.x;   // 0..127
    const int f = threadIdx.x;  // 0..63
    const int warp = f >> 5;
    const int lane = f & 31;

    float x0 = probes[b * HD + f];
    float x1 = probes[b * HD + NF + f];
    float ss = fmaf(x0, x0, x1 * x1);
#pragma unroll
    for (int o = 16; o; o >>= 1) ss += __shfl_xor_sync(0xffffffffu, ss, o);
    if (lane == 0) red[warp] = ss;
    __syncthreads();
    float inv = 1.0f / (sqrtf(red[0] + red[1]) + EPSF);

    float pr = x0 * inv;
    float pi = x1 * inv;
    float c, s;
    sincosf(angles[f], &s, &c);
    float Pr = pr * c - pi * s;
    float Pi = pr * s + pi * c;
    float xw = qw[b * NF + f];
    float sp = (xw > 20.0f) ? xw : log1pf(expf(xw));
    float w = -sp;
    float mw = qmw[b * NF + f];

    int p = b & 63;
    int hi = b >> 6;
    int base = (f * 64 + p) * 4;
    g_probeA[base + 0 + hi] = Pr;
    g_probeA[base + 2 + hi] = Pi;
    g_probeB[base + 0 + hi] = w;
    g_probeB[base + 2 + hi] = mw;
}

// ---------- SMEM layout (float offsets) ----------
#define OFF_SA  0                           // probeA: 16384 floats (64KB)
#define OFF_SB  16384                       // probeB: 16384 floats (64KB)
#define OFF_QT  32768                       // q-tables: 12 pairs * 5q * 64f * 4 = 15360 floats (60KB)
#define OFF_QN  48128                       // per-warp qn scratch: 24*128 = 3072 floats (12KB)
#define SMEM_FLOATS 51200                   // 200 KB

// f-loop over a batch of JN q's. Warp handles 32 b-pairs (p = lane + 32*h).
template<int JN>
__device__ __forceinline__ void run_batch(uint32_t aA0, uint32_t aB0, uint32_t aQT,
                                          u64 biasp, u64 EPS2,
                                          float* __restrict__ out, int q0, int p) {
    u64 acc[JN];
#pragma unroll
    for (int j = 0; j < JN; j++) acc[j] = biasp;

#pragma unroll 2
    for (int f = 0; f < NF; f++) {
        const uint32_t fo = (uint32_t)f * 1024u;
        u64 Pr, Pi, w, mw;
        asm("ld.shared.v2.b64 {%0,%1}, [%2];" : "=l"(Pr), "=l"(Pi) : "r"(aA0 + fo));
        asm("ld.shared.v2.b64 {%0,%1}, [%2];" : "=l"(w),  "=l"(mw) : "r"(aB0 + fo));

        float tx[JN], ty[JN], tz[JN], tw_[JN];
#pragma unroll
        for (int j = 0; j < JN; j++) {
            asm("ld.shared.v4.f32 {%0,%1,%2,%3}, [%4];"
                : "=f"(tx[j]), "=f"(ty[j]), "=f"(tz[j]), "=f"(tw_[j])
                : "r"(aQT + (uint32_t)j * 1024u + (uint32_t)f * 16u));
        }

#pragma unroll
        for (int j = 0; j < JN; j++) {
            u64 nqr = f2pk(tx[j], tx[j]);
            u64 nqi = f2pk(ty[j], ty[j]);
            u64 qm2 = f2pk(tz[j], tz[j]);
            u64 er = f2add(Pr, nqr);
            u64 ei = f2add(Pi, nqi);
            u64 d2 = f2fma(er, er, f2fma(ei, ei, EPS2));
            float lo, hi; f2upk(lo, hi, d2);
            u64 dist = f2pk(sqrt_apx(lo), sqrt_apx(hi));
            acc[j] = f2fma(dist, w, acc[j]);
            acc[j] = f2fma(qm2, mw, acc[j]);
        }
    }

#pragma unroll
    for (int j = 0; j < JN; j++) {
        float o0, o1; f2upk(o0, o1, acc[j]);
        float* orow = out + (size_t)(q0 + j) * NB;
        orow[p]      = o0;
        orow[p + 64] = o1;
    }
}

__global__ __launch_bounds__(THREADS, 1)
void main_kernel(const float* __restrict__ Q,
                 const float* __restrict__ bias,
                 float* __restrict__ out) {
    extern __shared__ float sm[];
    const int tid  = threadIdx.x;
    const int warp = tid >> 5;
    const int lane = tid & 31;
    const int pid  = warp >> 1;    // pair id 0..11
    const int h    = warp & 1;     // warp half within pair
    const int p    = lane + 32 * h; // b-pair index 0..63 handled by this lane

    // Stage probe tables into SMEM
    {
        const float4* gA = (const float4*)g_probeA;
        const float4* gB = (const float4*)g_probeB;
        float4* sA4 = (float4*)(sm + OFF_SA);
        float4* sB4 = (float4*)(sm + OFF_SB);
        for (int i = tid; i < NF * 64; i += THREADS) {
            sA4[i] = gA[i];
            sB4[i] = gB[i];
        }
    }

    const u64 biasp = f2pk(bias[p], bias[p + 64]);
    const u64 EPS2  = f2pk(EPSF, EPSF);

    __syncthreads();

    const uint32_t sbase = su32(sm);
    const uint32_t aA0 = sbase + (uint32_t)p * 16u;
    const uint32_t aB0 = sbase + (uint32_t)OFF_SB * 4u + (uint32_t)p * 16u;
    const uint32_t aQT = sbase + (uint32_t)OFF_QT * 4u + (uint32_t)pid * (MAXQ * 64u * 16u);
    float*  qn = sm + OFF_QN + warp * 128;
    float4* qt = (float4*)(sm + OFF_QT + pid * MAXQ * 64 * 4);

    // ---- contiguous q-range assignment per warp-pair (balanced to +/-1 q) ----
    const int npairs = gridDim.x * PAIRS_PER_CTA;
    const int gp = blockIdx.x * PAIRS_PER_CTA + pid;
    const int per = NQ / npairs;
    const int rem = NQ % npairs;
    int cnt, q0;
    if (gp < rem) { cnt = per + 1; q0 = gp * (per + 1); }
    else          { cnt = per;     q0 = rem * (per + 1) + (gp - rem) * per; }

    while (cnt > 0) {
        int jn = (cnt > MAXQ) ? 4 : cnt;   // 9 -> 4+5, 8 -> 4+4, small cnt -> exact

        // ---- batch prep: warps of the pair split the q's by parity of j ----
        for (int j = h; j < jn; j += 2) {
            const float4* Qv = (const float4*)(Q + (size_t)(q0 + j) * HD);
            float4 v = Qv[lane];
            float ss = fmaf(v.x, v.x, fmaf(v.y, v.y, fmaf(v.z, v.z, v.w * v.w)));
#pragma unroll
            for (int o = 16; o; o >>= 1) ss += __shfl_xor_sync(0xffffffffu, ss, o);
            float inv = rcp_apx(sqrt_apx(ss) + EPSF);
            ((float4*)qn)[lane] = make_float4(v.x * inv, v.y * inv, v.z * inv, v.w * inv);
            __syncwarp();
#pragma unroll
            for (int k = 0; k < 2; k++) {
                int f = lane + k * 32;
                float qr = qn[f];
                float qi = qn[f + 64];
                float qm = sqrt_apx(fmaf(qr, qr, fmaf(qi, qi, EPSF)));
                qt[j * 64 + f] = make_float4(-qr, -qi, qm, 0.0f);
            }
            __syncwarp();
        }
        // pair-scoped named barrier (ids 1..12; 0 reserved for __syncthreads)
        asm volatile("bar.sync %0, %1;" :: "r"(pid + 1), "r"(64) : "memory");

        switch (jn) {
            case 5: run_batch<5>(aA0, aB0, aQT, biasp, EPS2, out, q0, p); break;
            case 4: run_batch<4>(aA0, aB0, aQT, biasp, EPS2, out, q0, p); break;
            case 3: run_batch<3>(aA0, aB0, aQT, biasp, EPS2, out, q0, p); break;
            case 2: run_batch<2>(aA0, aB0, aQT, biasp, EPS2, out, q0, p); break;
            default: run_batch<1>(aA0, aB0, aQT, biasp, EPS2, out, q0, p); break;
        }

        // protect qt against next batch's overwrite while partner still reads
        asm volatile("bar.sync %0, %1;" :: "r"(pid + 1), "r"(64) : "memory");

        q0 += jn;
        cnt -= jn;
    }
}

extern "C" void kernel_launch(void* const* d_in, const int* in_sizes, int n_in,
                              void* d_out, int out_size) {
    const float* Q      = (const float*)d_in[0];
    const float* angles = (const float*)d_in[1];
    const float* probes = (const float*)d_in[2];
    const float* qw     = (const float*)d_in[3];
    const float* qmw    = (const float*)d_in[4];
    const float* qbias  = (const float*)d_in[5];
    float* out = (float*)d_out;

    static_assert(SMEM_FLOATS * sizeof(float) == 204800, "smem layout");
    static_assert(OFF_QT + PAIRS_PER_CTA * MAXQ * 64 * 4 <= OFF_QN, "qt overlap");
    static_assert(OFF_QN + WARPS_PER_CTA * 128 <= SMEM_FLOATS, "qn overlap");

    cudaFuncSetAttribute(main_kernel,
                         cudaFuncAttributeMaxDynamicSharedMemorySize,
                         SMEM_FLOATS * (int)sizeof(float));

    int sms = 148;
    cudaDeviceGetAttribute(&sms, cudaDevAttrMultiProcessorCount, 0);

    prep_kernel<<<NB, 64>>>(probes, angles, qw, qmw);
    main_kernel<<<sms, THREADS, SMEM_FLOATS * sizeof(float)>>>(Q, qbias, out);
}